// round 12
// baseline (speedup 1.0000x reference)
#include <cuda_runtime.h>
#include <math.h>

#define N_NODES 50000
#define N_EDGES 800000
#define DIM     128
#define HEADS   8
#define DK      16

// ---------------- scratch (no allocations allowed) ----------------
__device__ float g_qkv[(size_t)N_NODES * 384];   // [N][q(128) | k'(128) | v'(128)]
__device__ float g_t[(size_t)N_NODES * DIM];     // aggregated messages
__device__ float g_Wcat[128 * 384];              // fused [Wq | Wk@blkdiag(rel_att) | Wv@blkdiag(rel_msg)]
__device__ float g_bcat[384];
__device__ int   g_deg[N_NODES];
__device__ int   g_offs[N_NODES + 1];
__device__ int   g_cursor[N_NODES];
__device__ int   g_src_sorted[N_EDGES];

// ---------------- weight fusion ----------------
__global__ void prep_weights(const float* __restrict__ Wq, const float* __restrict__ bq,
                             const float* __restrict__ Wk, const float* __restrict__ bk,
                             const float* __restrict__ Wv, const float* __restrict__ bv,
                             const float* __restrict__ rel_att, const float* __restrict__ rel_msg)
{
    int idx = blockIdx.x * blockDim.x + threadIdx.x;
    if (idx < 128 * 384) {
        int k = idx / 384, c = idx % 384;
        float val;
        if (c < 128) {
            val = Wq[k * 128 + c];
        } else if (c < 256) {
            int cc = c - 128, hh = cc >> 4, j = cc & 15;
            float s = 0.f;
            #pragma unroll
            for (int l = 0; l < 16; l++)
                s += Wk[k * 128 + hh * 16 + l] * rel_att[hh * 256 + l * 16 + j];
            val = s;
        } else {
            int cc = c - 256, hh = cc >> 4, j = cc & 15;
            float s = 0.f;
            #pragma unroll
            for (int l = 0; l < 16; l++)
                s += Wv[k * 128 + hh * 16 + l] * rel_msg[hh * 256 + l * 16 + j];
            val = s;
        }
        g_Wcat[idx] = val;
    }
    if (idx < 384) {
        int c = idx;
        float val;
        if (c < 128) {
            val = bq[c];
        } else if (c < 256) {
            int cc = c - 128, hh = cc >> 4, j = cc & 15;
            float s = 0.f;
            #pragma unroll
            for (int l = 0; l < 16; l++)
                s += bk[hh * 16 + l] * rel_att[hh * 256 + l * 16 + j];
            val = s;
        } else {
            int cc = c - 256, hh = cc >> 4, j = cc & 15;
            float s = 0.f;
            #pragma unroll
            for (int l = 0; l < 16; l++)
                s += bv[hh * 16 + l] * rel_msg[hh * 256 + l * 16 + j];
            val = s;
        }
        g_bcat[c] = val;
    }
}

// ---------------- CSR build ----------------
__global__ void zero_deg(int n)
{
    int i = blockIdx.x * blockDim.x + threadIdx.x;
    if (i < n) g_deg[i] = 0;
}

__global__ void hist_kernel(const int* __restrict__ dst, int e)
{
    int i = blockIdx.x * blockDim.x + threadIdx.x;
    if (i < e) atomicAdd(&g_deg[dst[i]], 1);
}

#define SCAN_T 1024
__global__ void scan_kernel(int n)
{
    __shared__ int sums[SCAN_T];
    int t = threadIdx.x;
    int chunk = (n + SCAN_T - 1) / SCAN_T;
    int s = t * chunk;
    int e = min(s + chunk, n);
    int local = 0;
    for (int i = s; i < e; i++) local += g_deg[i];
    sums[t] = local;
    __syncthreads();
    for (int off = 1; off < SCAN_T; off <<= 1) {
        int v = (t >= off) ? sums[t - off] : 0;
        __syncthreads();
        sums[t] += v;
        __syncthreads();
    }
    int run = (t > 0) ? sums[t - 1] : 0;
    for (int i = s; i < e; i++) {
        g_offs[i] = run;
        g_cursor[i] = run;
        run += g_deg[i];
    }
    if (s < n && e == n) g_offs[n] = run;
}

__global__ void scatter_kernel(const int* __restrict__ src, const int* __restrict__ dst, int e)
{
    int i = blockIdx.x * blockDim.x + threadIdx.x;
    if (i < e) {
        int pos = atomicAdd(&g_cursor[dst[i]], 1);
        g_src_sorted[pos] = src[i];
    }
}

// ---------------- SIMT fp32 GEMM: C[M,N] = A[M,K] @ B[K,N] + bias, optional skip-mix epilogue ----------------
#define BM 64
#define BN 128
#define BK 32
#define TM 8
#define TN 4
// 256 threads: (BM/TM)=8 row groups x (BN/TN)=32 col groups

__global__ void gemm_kernel(const float* __restrict__ A, const float* __restrict__ B,
                            const float* __restrict__ bias, float* __restrict__ C,
                            int M, int N, int K,
                            const float* __restrict__ skip, const float* __restrict__ resid)
{
    __shared__ float As[BK][BM + 4];
    __shared__ float Bs[BK][BN];

    int tid = threadIdx.x;
    int block_row = blockIdx.y * BM;
    int block_col = blockIdx.x * BN;
    int tcol = tid & 31;   // 0..31 -> cols tcol*4..+3
    int trow = tid >> 5;   // 0..7  -> rows trow*8..+7

    float acc[TM][TN];
    #pragma unroll
    for (int i = 0; i < TM; i++)
        #pragma unroll
        for (int j = 0; j < TN; j++) acc[i][j] = 0.f;

    for (int k0 = 0; k0 < K; k0 += BK) {
        // A tile: BM x BK = 512 float4
        #pragma unroll
        for (int it = 0; it < 2; it++) {
            int idx = tid + it * 256;          // 0..511
            int r  = idx >> 3;                 // 0..63
            int kk = (idx & 7) * 4;            // 0,4,...,28
            int grow = block_row + r;
            float4 v = make_float4(0.f, 0.f, 0.f, 0.f);
            if (grow < M) v = *(const float4*)&A[(size_t)grow * K + k0 + kk];
            As[kk + 0][r] = v.x;
            As[kk + 1][r] = v.y;
            As[kk + 2][r] = v.z;
            As[kk + 3][r] = v.w;
        }
        // B tile: BK x BN = 1024 float4
        #pragma unroll
        for (int it = 0; it < 4; it++) {
            int idx = tid + it * 256;          // 0..1023
            int kk = idx >> 5;                 // 0..31
            int c  = (idx & 31) * 4;
            *(float4*)&Bs[kk][c] = *(const float4*)&B[(size_t)(k0 + kk) * N + block_col + c];
        }
        __syncthreads();

        #pragma unroll 8
        for (int kk = 0; kk < BK; kk++) {
            float4 a0 = *(const float4*)&As[kk][trow * TM];
            float4 a1 = *(const float4*)&As[kk][trow * TM + 4];
            float4 b0 = *(const float4*)&Bs[kk][tcol * TN];
            float a[TM] = {a0.x, a0.y, a0.z, a0.w, a1.x, a1.y, a1.z, a1.w};
            float b[TN] = {b0.x, b0.y, b0.z, b0.w};
            #pragma unroll
            for (int i = 0; i < TM; i++)
                #pragma unroll
                for (int j = 0; j < TN; j++)
                    acc[i][j] = fmaf(a[i], b[j], acc[i][j]);
        }
        __syncthreads();
    }

    float alpha = 1.f, beta = 0.f;
    if (skip) {
        float a = 1.f / (1.f + __expf(-skip[0]));
        alpha = a;
        beta = 1.f - a;
    }
    int gcol = block_col + tcol * TN;
    float4 bb = *(const float4*)&bias[gcol];
    #pragma unroll
    for (int i = 0; i < TM; i++) {
        int grow = block_row + trow * TM + i;
        if (grow < M) {
            float4 r;
            r.x = acc[i][0] + bb.x;
            r.y = acc[i][1] + bb.y;
            r.z = acc[i][2] + bb.z;
            r.w = acc[i][3] + bb.w;
            if (skip) {
                const float4 h4 = *(const float4*)&resid[(size_t)grow * N + gcol];
                r.x = r.x * alpha + h4.x * beta;
                r.y = r.y * alpha + h4.y * beta;
                r.z = r.z * alpha + h4.z * beta;
                r.w = r.w * alpha + h4.w * beta;
            }
            *(float4*)&C[(size_t)grow * N + gcol] = r;
        }
    }
}

// ---------------- fused per-node online-softmax aggregation ----------------
// One warp per dst node. lane l owns dims 4l..4l+3 (head = l>>2).
__global__ void attn_kernel(const float* __restrict__ rel_pri, int n)
{
    int warp = (blockIdx.x * blockDim.x + threadIdx.x) >> 5;
    if (warp >= n) return;
    int lane = threadIdx.x & 31;
    int head = lane >> 2;

    const float qs = rel_pri[head] * 0.25f;   // rel_pri / sqrt(DK)
    float4 q = *(const float4*)&g_qkv[(size_t)warp * 384 + lane * 4];
    q.x *= qs; q.y *= qs; q.z *= qs; q.w *= qs;

    float m = -INFINITY, ssum = 0.f;
    float4 acc = make_float4(0.f, 0.f, 0.f, 0.f);

    int e0 = g_offs[warp], e1 = g_offs[warp + 1];
    for (int e = e0; e < e1; e++) {
        int s = g_src_sorted[e];
        const float* row = &g_qkv[(size_t)s * 384];
        float4 k4 = *(const float4*)&row[128 + lane * 4];
        float p = q.x * k4.x + q.y * k4.y + q.z * k4.z + q.w * k4.w;
        p += __shfl_xor_sync(0xffffffffu, p, 1);
        p += __shfl_xor_sync(0xffffffffu, p, 2);   // all 4 lanes of a head hold the full dot
        float nm = fmaxf(m, p);
        float scale = __expf(m - nm);              // 0 on first edge (m = -inf)
        float w = __expf(p - nm);
        m = nm;
        ssum = ssum * scale + w;
        float4 v4 = *(const float4*)&row[256 + lane * 4];
        acc.x = acc.x * scale + w * v4.x;
        acc.y = acc.y * scale + w * v4.y;
        acc.z = acc.z * scale + w * v4.z;
        acc.w = acc.w * scale + w * v4.w;
    }
    float inv = (ssum > 0.f) ? (1.f / ssum) : 0.f;  // empty segment -> zeros (matches reference)
    float4 out = make_float4(acc.x * inv, acc.y * inv, acc.z * inv, acc.w * inv);
    *(float4*)&g_t[(size_t)warp * DIM + lane * 4] = out;
}

// ---------------- launcher ----------------
extern "C" void kernel_launch(void* const* d_in, const int* in_sizes, int n_in,
                              void* d_out, int out_size)
{
    const float* h       = (const float*)d_in[0];
    const int*   src     = (const int*)  d_in[1];
    const int*   dst     = (const int*)  d_in[2];
    const float* Wk      = (const float*)d_in[3];
    const float* bk      = (const float*)d_in[4];
    const float* Wq      = (const float*)d_in[5];
    const float* bq      = (const float*)d_in[6];
    const float* Wv      = (const float*)d_in[7];
    const float* bv      = (const float*)d_in[8];
    const float* Wa      = (const float*)d_in[9];
    const float* ba      = (const float*)d_in[10];
    const float* rel_att = (const float*)d_in[11];
    const float* rel_msg = (const float*)d_in[12];
    const float* rel_pri = (const float*)d_in[13];
    const float* skip    = (const float*)d_in[14];
    float* out = (float*)d_out;

    int n = in_sizes[0] / DIM;   // 50000
    int e = in_sizes[1];         // 800000

    float *qkv, *t, *Wcat, *bcat;
    cudaGetSymbolAddress((void**)&qkv,  g_qkv);
    cudaGetSymbolAddress((void**)&t,    g_t);
    cudaGetSymbolAddress((void**)&Wcat, g_Wcat);
    cudaGetSymbolAddress((void**)&bcat, g_bcat);

    // 1) fuse rel_att/rel_msg into projection weights
    prep_weights<<<(128 * 384 + 255) / 256, 256>>>(Wq, bq, Wk, bk, Wv, bv, rel_att, rel_msg);

    // 2) CSR by dst
    zero_deg<<<(n + 255) / 256, 256>>>(n);
    hist_kernel<<<(e + 255) / 256, 256>>>(dst, e);
    scan_kernel<<<1, SCAN_T>>>(n);
    scatter_kernel<<<(e + 255) / 256, 256>>>(src, dst, e);

    // 3) fused projection GEMM: [n,128] @ [128,384] -> q | k' | v'
    {
        dim3 grid(384 / BN, (n + BM - 1) / BM);
        gemm_kernel<<<grid, 256>>>(h, Wcat, bcat, qkv, n, 384, DIM, nullptr, nullptr);
    }

    // 4) per-node online-softmax attention + aggregation
    attn_kernel<<<(n * 32 + 255) / 256, 256>>>(rel_pri, n);

    // 5) output GEMM with skip-mix epilogue: out = (t@Wa + ba)*sigmoid(skip) + h*(1-sigmoid(skip))
    {
        dim3 grid(DIM / BN, (n + BM - 1) / BM);
        gemm_kernel<<<grid, 256>>>(t, Wa, ba, out, n, DIM, DIM, skip, h);
    }
}

// round 13
// speedup vs baseline: 1.2749x; 1.2749x over previous
#include <cuda_runtime.h>
#include <math.h>

#define N_NODES 50000
#define N_EDGES 800000
#define DIM     128
#define HEADS   8
#define DK      16

// ---------------- scratch (no allocations allowed) ----------------
__device__ float g_qkv[(size_t)N_NODES * 384];   // [N][q(128) | k'(128) | v'(128)]
__device__ float g_t[(size_t)N_NODES * DIM];     // aggregated messages
__device__ float g_Wcat[128 * 384];              // fused [Wq | Wk@blkdiag(rel_att) | Wv@blkdiag(rel_msg)]
__device__ float g_bcat[384];
__device__ int   g_deg[N_NODES];
__device__ int   g_offs[N_NODES];
__device__ int   g_cursor[N_NODES];
__device__ int   g_src_sorted[N_EDGES];
__device__ int   g_total;

// ---------------- weight fusion ----------------
__global__ void prep_weights(const float* __restrict__ Wq, const float* __restrict__ bq,
                             const float* __restrict__ Wk, const float* __restrict__ bk,
                             const float* __restrict__ Wv, const float* __restrict__ bv,
                             const float* __restrict__ rel_att, const float* __restrict__ rel_msg)
{
    int idx = blockIdx.x * blockDim.x + threadIdx.x;
    if (idx < 128 * 384) {
        int k = idx / 384, c = idx % 384;
        float val;
        if (c < 128) {
            val = Wq[k * 128 + c];
        } else if (c < 256) {
            int cc = c - 128, hh = cc >> 4, j = cc & 15;
            float s = 0.f;
            #pragma unroll
            for (int l = 0; l < 16; l++)
                s += Wk[k * 128 + hh * 16 + l] * rel_att[hh * 256 + l * 16 + j];
            val = s;
        } else {
            int cc = c - 256, hh = cc >> 4, j = cc & 15;
            float s = 0.f;
            #pragma unroll
            for (int l = 0; l < 16; l++)
                s += Wv[k * 128 + hh * 16 + l] * rel_msg[hh * 256 + l * 16 + j];
            val = s;
        }
        g_Wcat[idx] = val;
    }
    if (idx < 384) {
        int c = idx;
        float val;
        if (c < 128) {
            val = bq[c];
        } else if (c < 256) {
            int cc = c - 128, hh = cc >> 4, j = cc & 15;
            float s = 0.f;
            #pragma unroll
            for (int l = 0; l < 16; l++)
                s += bk[hh * 16 + l] * rel_att[hh * 256 + l * 16 + j];
            val = s;
        } else {
            int cc = c - 256, hh = cc >> 4, j = cc & 15;
            float s = 0.f;
            #pragma unroll
            for (int l = 0; l < 16; l++)
                s += bv[hh * 16 + l] * rel_msg[hh * 256 + l * 16 + j];
            val = s;
        }
        g_bcat[c] = val;
    }
}

// ---------------- CSR build ----------------
__global__ void zero_deg(int n)
{
    int i = blockIdx.x * blockDim.x + threadIdx.x;
    if (i < n) g_deg[i] = 0;
    if (i == 0) g_total = 0;
}

__global__ void hist_kernel(const int* __restrict__ dst, int e)
{
    int i = blockIdx.x * blockDim.x + threadIdx.x;
    if (i < e) atomicAdd(&g_deg[dst[i]], 1);
}

// Warp-aggregated range allocation: replaces the global prefix scan.
// Segment bases are in arbitrary order -- each node just needs a contiguous
// range [offs[i], offs[i]+deg[i]) in g_src_sorted, which is all attn needs.
__global__ void alloc_kernel(int n)
{
    int i = blockIdx.x * blockDim.x + threadIdx.x;
    int lane = threadIdx.x & 31;
    int d = (i < n) ? g_deg[i] : 0;
    int incl = d;
    #pragma unroll
    for (int off = 1; off < 32; off <<= 1) {
        int v = __shfl_up_sync(0xffffffffu, incl, off);
        if (lane >= off) incl += v;
    }
    int wtot = __shfl_sync(0xffffffffu, incl, 31);
    int base = 0;
    if (lane == 31 && wtot > 0) base = atomicAdd(&g_total, wtot);
    base = __shfl_sync(0xffffffffu, base, 31);
    if (i < n) {
        int off = base + incl - d;
        g_offs[i] = off;
        g_cursor[i] = off;
    }
}

__global__ void scatter_kernel(const int* __restrict__ src, const int* __restrict__ dst, int e)
{
    int i = blockIdx.x * blockDim.x + threadIdx.x;
    if (i < e) {
        int pos = atomicAdd(&g_cursor[dst[i]], 1);
        g_src_sorted[pos] = src[i];
    }
}

// ---------------- SIMT fp32 GEMM: C[M,N] = A[M,K] @ B[K,N] + bias, optional skip-mix epilogue ----------------
#define BM 64
#define BN 128
#define BK 32
#define TM 8
#define TN 4
// 256 threads: (BM/TM)=8 row groups x (BN/TN)=32 col groups

__global__ void gemm_kernel(const float* __restrict__ A, const float* __restrict__ B,
                            const float* __restrict__ bias, float* __restrict__ C,
                            int M, int N, int K,
                            const float* __restrict__ skip, const float* __restrict__ resid)
{
    __shared__ float As[BK][BM + 4];
    __shared__ float Bs[BK][BN];

    int tid = threadIdx.x;
    int block_row = blockIdx.y * BM;
    int block_col = blockIdx.x * BN;
    int tcol = tid & 31;   // 0..31 -> cols tcol*4..+3
    int trow = tid >> 5;   // 0..7  -> rows trow*8..+7

    float acc[TM][TN];
    #pragma unroll
    for (int i = 0; i < TM; i++)
        #pragma unroll
        for (int j = 0; j < TN; j++) acc[i][j] = 0.f;

    for (int k0 = 0; k0 < K; k0 += BK) {
        // A tile: BM x BK = 512 float4
        #pragma unroll
        for (int it = 0; it < 2; it++) {
            int idx = tid + it * 256;          // 0..511
            int r  = idx >> 3;                 // 0..63
            int kk = (idx & 7) * 4;            // 0,4,...,28
            int grow = block_row + r;
            float4 v = make_float4(0.f, 0.f, 0.f, 0.f);
            if (grow < M) v = *(const float4*)&A[(size_t)grow * K + k0 + kk];
            As[kk + 0][r] = v.x;
            As[kk + 1][r] = v.y;
            As[kk + 2][r] = v.z;
            As[kk + 3][r] = v.w;
        }
        // B tile: BK x BN = 1024 float4
        #pragma unroll
        for (int it = 0; it < 4; it++) {
            int idx = tid + it * 256;          // 0..1023
            int kk = idx >> 5;                 // 0..31
            int c  = (idx & 31) * 4;
            *(float4*)&Bs[kk][c] = *(const float4*)&B[(size_t)(k0 + kk) * N + block_col + c];
        }
        __syncthreads();

        #pragma unroll 8
        for (int kk = 0; kk < BK; kk++) {
            float4 a0 = *(const float4*)&As[kk][trow * TM];
            float4 a1 = *(const float4*)&As[kk][trow * TM + 4];
            float4 b0 = *(const float4*)&Bs[kk][tcol * TN];
            float a[TM] = {a0.x, a0.y, a0.z, a0.w, a1.x, a1.y, a1.z, a1.w};
            float b[TN] = {b0.x, b0.y, b0.z, b0.w};
            #pragma unroll
            for (int i = 0; i < TM; i++)
                #pragma unroll
                for (int j = 0; j < TN; j++)
                    acc[i][j] = fmaf(a[i], b[j], acc[i][j]);
        }
        __syncthreads();
    }

    float alpha = 1.f, beta = 0.f;
    if (skip) {
        float a = 1.f / (1.f + __expf(-skip[0]));
        alpha = a;
        beta = 1.f - a;
    }
    int gcol = block_col + tcol * TN;
    float4 bb = *(const float4*)&bias[gcol];
    #pragma unroll
    for (int i = 0; i < TM; i++) {
        int grow = block_row + trow * TM + i;
        if (grow < M) {
            float4 r;
            r.x = acc[i][0] + bb.x;
            r.y = acc[i][1] + bb.y;
            r.z = acc[i][2] + bb.z;
            r.w = acc[i][3] + bb.w;
            if (skip) {
                const float4 h4 = *(const float4*)&resid[(size_t)grow * N + gcol];
                r.x = r.x * alpha + h4.x * beta;
                r.y = r.y * alpha + h4.y * beta;
                r.z = r.z * alpha + h4.z * beta;
                r.w = r.w * alpha + h4.w * beta;
            }
            *(float4*)&C[(size_t)grow * N + gcol] = r;
        }
    }
}

// ---------------- fused per-node online-softmax aggregation ----------------
// One warp per dst node. lane l owns dims 4l..4l+3 (head = l>>2).
__global__ void attn_kernel(const float* __restrict__ rel_pri, int n)
{
    int warp = (blockIdx.x * blockDim.x + threadIdx.x) >> 5;
    if (warp >= n) return;
    int lane = threadIdx.x & 31;
    int head = lane >> 2;

    const float qs = rel_pri[head] * 0.25f;   // rel_pri / sqrt(DK)
    float4 q = *(const float4*)&g_qkv[(size_t)warp * 384 + lane * 4];
    q.x *= qs; q.y *= qs; q.z *= qs; q.w *= qs;

    float m = -INFINITY, ssum = 0.f;
    float4 acc = make_float4(0.f, 0.f, 0.f, 0.f);

    int e0 = g_offs[warp], e1 = e0 + g_deg[warp];
    for (int e = e0; e < e1; e++) {
        int s = g_src_sorted[e];
        const float* row = &g_qkv[(size_t)s * 384];
        float4 k4 = *(const float4*)&row[128 + lane * 4];
        float p = q.x * k4.x + q.y * k4.y + q.z * k4.z + q.w * k4.w;
        p += __shfl_xor_sync(0xffffffffu, p, 1);
        p += __shfl_xor_sync(0xffffffffu, p, 2);   // all 4 lanes of a head hold the full dot
        float nm = fmaxf(m, p);
        float scale = __expf(m - nm);              // 0 on first edge (m = -inf)
        float w = __expf(p - nm);
        m = nm;
        ssum = ssum * scale + w;
        float4 v4 = *(const float4*)&row[256 + lane * 4];
        acc.x = acc.x * scale + w * v4.x;
        acc.y = acc.y * scale + w * v4.y;
        acc.z = acc.z * scale + w * v4.z;
        acc.w = acc.w * scale + w * v4.w;
    }
    float inv = (ssum > 0.f) ? (1.f / ssum) : 0.f;  // empty segment -> zeros (matches reference)
    float4 out = make_float4(acc.x * inv, acc.y * inv, acc.z * inv, acc.w * inv);
    *(float4*)&g_t[(size_t)warp * DIM + lane * 4] = out;
}

// ---------------- launcher ----------------
extern "C" void kernel_launch(void* const* d_in, const int* in_sizes, int n_in,
                              void* d_out, int out_size)
{
    const float* h       = (const float*)d_in[0];
    const int*   src     = (const int*)  d_in[1];
    const int*   dst     = (const int*)  d_in[2];
    const float* Wk      = (const float*)d_in[3];
    const float* bk      = (const float*)d_in[4];
    const float* Wq      = (const float*)d_in[5];
    const float* bq      = (const float*)d_in[6];
    const float* Wv      = (const float*)d_in[7];
    const float* bv      = (const float*)d_in[8];
    const float* Wa      = (const float*)d_in[9];
    const float* ba      = (const float*)d_in[10];
    const float* rel_att = (const float*)d_in[11];
    const float* rel_msg = (const float*)d_in[12];
    const float* rel_pri = (const float*)d_in[13];
    const float* skip    = (const float*)d_in[14];
    float* out = (float*)d_out;

    int n = in_sizes[0] / DIM;   // 50000
    int e = in_sizes[1];         // 800000

    float *qkv, *t;
    cudaGetSymbolAddress((void**)&qkv, g_qkv);
    cudaGetSymbolAddress((void**)&t,   g_t);
    float *Wcat, *bcat;
    cudaGetSymbolAddress((void**)&Wcat, g_Wcat);
    cudaGetSymbolAddress((void**)&bcat, g_bcat);

    // 1) fuse rel_att/rel_msg into projection weights
    prep_weights<<<(128 * 384 + 255) / 256, 256>>>(Wq, bq, Wk, bk, Wv, bv, rel_att, rel_msg);

    // 2) CSR by dst (warp-aggregated range allocation instead of global scan)
    zero_deg<<<(n + 255) / 256, 256>>>(n);
    hist_kernel<<<(e + 255) / 256, 256>>>(dst, e);
    alloc_kernel<<<(n + 255) / 256, 256>>>(n);
    scatter_kernel<<<(e + 255) / 256, 256>>>(src, dst, e);

    // 3) fused projection GEMM: [n,128] @ [128,384] -> q | k' | v'
    {
        dim3 grid(384 / BN, (n + BM - 1) / BM);
        gemm_kernel<<<grid, 256>>>(h, Wcat, bcat, qkv, n, 384, DIM, nullptr, nullptr);
    }

    // 4) per-node online-softmax attention + aggregation
    attn_kernel<<<(n * 32 + 255) / 256, 256>>>(rel_pri, n);

    // 5) output GEMM with skip-mix epilogue: out = (t@Wa + ba)*sigmoid(skip) + h*(1-sigmoid(skip))
    {
        dim3 grid(DIM / BN, (n + BM - 1) / BM);
        gemm_kernel<<<grid, 256>>>(t, Wa, ba, out, n, DIM, DIM, skip, h);
    }
}

// round 14
// speedup vs baseline: 1.3358x; 1.0478x over previous
#include <cuda_runtime.h>
#include <math.h>

#define N_NODES 50000
#define N_EDGES 800000
#define DIM     128
#define HEADS   8
#define DK      16

// ---------------- scratch (no allocations allowed) ----------------
__device__ float g_qkv[(size_t)N_NODES * 384];   // [N][q(128) | k'(128) | v'(128)]
__device__ float g_t[(size_t)N_NODES * DIM];     // aggregated messages
__device__ float g_Wcat[128 * 384];              // fused [Wq | Wk@blkdiag(rel_att) | Wv@blkdiag(rel_msg)]
__device__ float g_bcat[384];
__device__ int   g_deg[N_NODES];
__device__ int   g_offs[N_NODES];
__device__ int   g_cursor[N_NODES];
__device__ int   g_src_sorted[N_EDGES];
__device__ int   g_total;

// ---------------- weight fusion ----------------
__global__ void prep_weights(const float* __restrict__ Wq, const float* __restrict__ bq,
                             const float* __restrict__ Wk, const float* __restrict__ bk,
                             const float* __restrict__ Wv, const float* __restrict__ bv,
                             const float* __restrict__ rel_att, const float* __restrict__ rel_msg)
{
    int idx = blockIdx.x * blockDim.x + threadIdx.x;
    if (idx < 128 * 384) {
        int k = idx / 384, c = idx % 384;
        float val;
        if (c < 128) {
            val = Wq[k * 128 + c];
        } else if (c < 256) {
            int cc = c - 128, hh = cc >> 4, j = cc & 15;
            float s = 0.f;
            #pragma unroll
            for (int l = 0; l < 16; l++)
                s += Wk[k * 128 + hh * 16 + l] * rel_att[hh * 256 + l * 16 + j];
            val = s;
        } else {
            int cc = c - 256, hh = cc >> 4, j = cc & 15;
            float s = 0.f;
            #pragma unroll
            for (int l = 0; l < 16; l++)
                s += Wv[k * 128 + hh * 16 + l] * rel_msg[hh * 256 + l * 16 + j];
            val = s;
        }
        g_Wcat[idx] = val;
    }
    if (idx < 384) {
        int c = idx;
        float val;
        if (c < 128) {
            val = bq[c];
        } else if (c < 256) {
            int cc = c - 128, hh = cc >> 4, j = cc & 15;
            float s = 0.f;
            #pragma unroll
            for (int l = 0; l < 16; l++)
                s += bk[hh * 16 + l] * rel_att[hh * 256 + l * 16 + j];
            val = s;
        } else {
            int cc = c - 256, hh = cc >> 4, j = cc & 15;
            float s = 0.f;
            #pragma unroll
            for (int l = 0; l < 16; l++)
                s += bv[hh * 16 + l] * rel_msg[hh * 256 + l * 16 + j];
            val = s;
        }
        g_bcat[c] = val;
    }
}

// ---------------- CSR build ----------------
__global__ void zero_deg(int n)
{
    int i = blockIdx.x * blockDim.x + threadIdx.x;
    if (i < n) g_deg[i] = 0;
    if (i == 0) g_total = 0;
}

__global__ void hist_kernel(const int* __restrict__ dst, int e)
{
    int i = blockIdx.x * blockDim.x + threadIdx.x;
    if (i < e) atomicAdd(&g_deg[dst[i]], 1);
}

// Warp-aggregated range allocation (segment bases in arbitrary order).
__global__ void alloc_kernel(int n)
{
    int i = blockIdx.x * blockDim.x + threadIdx.x;
    int lane = threadIdx.x & 31;
    int d = (i < n) ? g_deg[i] : 0;
    int incl = d;
    #pragma unroll
    for (int off = 1; off < 32; off <<= 1) {
        int v = __shfl_up_sync(0xffffffffu, incl, off);
        if (lane >= off) incl += v;
    }
    int wtot = __shfl_sync(0xffffffffu, incl, 31);
    int base = 0;
    if (lane == 31 && wtot > 0) base = atomicAdd(&g_total, wtot);
    base = __shfl_sync(0xffffffffu, base, 31);
    if (i < n) {
        int off = base + incl - d;
        g_offs[i] = off;
        g_cursor[i] = off;
    }
}

__global__ void scatter_kernel(const int* __restrict__ src, const int* __restrict__ dst, int e)
{
    int i = blockIdx.x * blockDim.x + threadIdx.x;
    if (i < e) {
        int pos = atomicAdd(&g_cursor[dst[i]], 1);
        g_src_sorted[pos] = src[i];
    }
}

// ---------------- SIMT fp32 GEMM with packed FFMA2 (fma.rn.f32x2) ----------------
#define BM 64
#define BN 128
#define BK 32
#define TM 8
#define TN 4
// 256 threads: trow=tid>>5 (8 row groups of TM=8), tcol=tid&31 (32 col groups of TN=4)
// Accumulators are M-adjacent row PAIRS packed into b64: acc2[pi][j] holds
// rows (trow*8 + 2*pi, +1), col (tcol*4 + j). Bit-identical to scalar FFMA.

#define FMA2(d, a, b) asm("fma.rn.f32x2 %0, %1, %2, %0;" : "+l"(d) : "l"(a), "l"(b))
#define PACK2(d, lo, hi) asm("mov.b64 %0, {%1, %2};" : "=l"(d) : "f"(lo), "f"(hi))
#define DUP2(d, v) asm("mov.b64 %0, {%1, %1};" : "=l"(d) : "f"(v))
#define UNPACK2(lo, hi, s) asm("mov.b64 {%0, %1}, %2;" : "=f"(lo), "=f"(hi) : "l"(s))

__global__ void gemm_kernel(const float* __restrict__ A, const float* __restrict__ B,
                            const float* __restrict__ bias, float* __restrict__ C,
                            int M, int N, int K,
                            const float* __restrict__ skip, const float* __restrict__ resid)
{
    __shared__ float As[BK][BM + 4];
    __shared__ float Bs[BK][BN];

    int tid = threadIdx.x;
    int block_row = blockIdx.y * BM;
    int block_col = blockIdx.x * BN;
    int tcol = tid & 31;
    int trow = tid >> 5;

    unsigned long long acc2[4][TN];
    #pragma unroll
    for (int i = 0; i < 4; i++)
        #pragma unroll
        for (int j = 0; j < TN; j++) acc2[i][j] = 0ull;   // {0.f, 0.f}

    for (int k0 = 0; k0 < K; k0 += BK) {
        // A tile: BM x BK = 512 float4 loads (transposed into As[k][m])
        #pragma unroll
        for (int it = 0; it < 2; it++) {
            int idx = tid + it * 256;
            int r  = idx >> 3;
            int kk = (idx & 7) * 4;
            int grow = block_row + r;
            float4 v = make_float4(0.f, 0.f, 0.f, 0.f);
            if (grow < M) v = *(const float4*)&A[(size_t)grow * K + k0 + kk];
            As[kk + 0][r] = v.x;
            As[kk + 1][r] = v.y;
            As[kk + 2][r] = v.z;
            As[kk + 3][r] = v.w;
        }
        // B tile: BK x BN = 1024 float4 loads
        #pragma unroll
        for (int it = 0; it < 4; it++) {
            int idx = tid + it * 256;
            int kk = idx >> 5;
            int c  = (idx & 31) * 4;
            *(float4*)&Bs[kk][c] = *(const float4*)&B[(size_t)(k0 + kk) * N + block_col + c];
        }
        __syncthreads();

        #pragma unroll 8
        for (int kk = 0; kk < BK; kk++) {
            float4 a0 = *(const float4*)&As[kk][trow * TM];       // warp-uniform (broadcast)
            float4 a1 = *(const float4*)&As[kk][trow * TM + 4];
            float4 b0 = *(const float4*)&Bs[kk][tcol * TN];
            unsigned long long pa0, pa1, pa2, pa3;
            unsigned long long db0, db1, db2, db3;
            PACK2(pa0, a0.x, a0.y);   // adjacent regs from the float4 -> cheap pair
            PACK2(pa1, a0.z, a0.w);
            PACK2(pa2, a1.x, a1.y);
            PACK2(pa3, a1.z, a1.w);
            DUP2(db0, b0.x);
            DUP2(db1, b0.y);
            DUP2(db2, b0.z);
            DUP2(db3, b0.w);
            FMA2(acc2[0][0], pa0, db0); FMA2(acc2[0][1], pa0, db1);
            FMA2(acc2[0][2], pa0, db2); FMA2(acc2[0][3], pa0, db3);
            FMA2(acc2[1][0], pa1, db0); FMA2(acc2[1][1], pa1, db1);
            FMA2(acc2[1][2], pa1, db2); FMA2(acc2[1][3], pa1, db3);
            FMA2(acc2[2][0], pa2, db0); FMA2(acc2[2][1], pa2, db1);
            FMA2(acc2[2][2], pa2, db2); FMA2(acc2[2][3], pa2, db3);
            FMA2(acc2[3][0], pa3, db0); FMA2(acc2[3][1], pa3, db1);
            FMA2(acc2[3][2], pa3, db2); FMA2(acc2[3][3], pa3, db3);
        }
        __syncthreads();
    }

    float alpha = 1.f, beta = 0.f;
    if (skip) {
        float a = 1.f / (1.f + __expf(-skip[0]));
        alpha = a;
        beta = 1.f - a;
    }
    int gcol = block_col + tcol * TN;
    float4 bb = *(const float4*)&bias[gcol];
    #pragma unroll
    for (int pi = 0; pi < 4; pi++) {
        float r0[TN], r1[TN];
        #pragma unroll
        for (int j = 0; j < TN; j++) UNPACK2(r0[j], r1[j], acc2[pi][j]);
        #pragma unroll
        for (int half = 0; half < 2; half++) {
            int grow = block_row + trow * TM + 2 * pi + half;
            if (grow < M) {
                float* rr = half ? r1 : r0;
                float4 r;
                r.x = rr[0] + bb.x;
                r.y = rr[1] + bb.y;
                r.z = rr[2] + bb.z;
                r.w = rr[3] + bb.w;
                if (skip) {
                    const float4 h4 = *(const float4*)&resid[(size_t)grow * N + gcol];
                    r.x = r.x * alpha + h4.x * beta;
                    r.y = r.y * alpha + h4.y * beta;
                    r.z = r.z * alpha + h4.z * beta;
                    r.w = r.w * alpha + h4.w * beta;
                }
                *(float4*)&C[(size_t)grow * N + gcol] = r;
            }
        }
    }
}

// ---------------- fused per-node online-softmax aggregation ----------------
// One warp per dst node. lane l owns dims 4l..4l+3 (head = l>>2).
__global__ void attn_kernel(const float* __restrict__ rel_pri, int n)
{
    int warp = (blockIdx.x * blockDim.x + threadIdx.x) >> 5;
    if (warp >= n) return;
    int lane = threadIdx.x & 31;
    int head = lane >> 2;

    const float qs = rel_pri[head] * 0.25f;   // rel_pri / sqrt(DK)
    float4 q = *(const float4*)&g_qkv[(size_t)warp * 384 + lane * 4];
    q.x *= qs; q.y *= qs; q.z *= qs; q.w *= qs;

    float m = -INFINITY, ssum = 0.f;
    float4 acc = make_float4(0.f, 0.f, 0.f, 0.f);

    int e0 = g_offs[warp], e1 = e0 + g_deg[warp];
    int s_next = (e0 < e1) ? g_src_sorted[e0] : 0;   // prefetch index
    for (int e = e0; e < e1; e++) {
        int s = s_next;
        if (e + 1 < e1) s_next = g_src_sorted[e + 1]; // overlap next index fetch
        const float* row = &g_qkv[(size_t)s * 384];
        float4 k4 = *(const float4*)&row[128 + lane * 4];
        float4 v4 = *(const float4*)&row[256 + lane * 4];  // issue both loads up front
        float p = q.x * k4.x + q.y * k4.y + q.z * k4.z + q.w * k4.w;
        p += __shfl_xor_sync(0xffffffffu, p, 1);
        p += __shfl_xor_sync(0xffffffffu, p, 2);   // all 4 lanes of a head hold the full dot
        float nm = fmaxf(m, p);
        float scale = __expf(m - nm);              // 0 on first edge (m = -inf)
        float w = __expf(p - nm);
        m = nm;
        ssum = ssum * scale + w;
        acc.x = acc.x * scale + w * v4.x;
        acc.y = acc.y * scale + w * v4.y;
        acc.z = acc.z * scale + w * v4.z;
        acc.w = acc.w * scale + w * v4.w;
    }
    float inv = (ssum > 0.f) ? (1.f / ssum) : 0.f;  // empty segment -> zeros (matches reference)
    float4 out = make_float4(acc.x * inv, acc.y * inv, acc.z * inv, acc.w * inv);
    *(float4*)&g_t[(size_t)warp * DIM + lane * 4] = out;
}

// ---------------- launcher ----------------
extern "C" void kernel_launch(void* const* d_in, const int* in_sizes, int n_in,
                              void* d_out, int out_size)
{
    const float* h       = (const float*)d_in[0];
    const int*   src     = (const int*)  d_in[1];
    const int*   dst     = (const int*)  d_in[2];
    const float* Wk      = (const float*)d_in[3];
    const float* bk      = (const float*)d_in[4];
    const float* Wq      = (const float*)d_in[5];
    const float* bq      = (const float*)d_in[6];
    const float* Wv      = (const float*)d_in[7];
    const float* bv      = (const float*)d_in[8];
    const float* Wa      = (const float*)d_in[9];
    const float* ba      = (const float*)d_in[10];
    const float* rel_att = (const float*)d_in[11];
    const float* rel_msg = (const float*)d_in[12];
    const float* rel_pri = (const float*)d_in[13];
    const float* skip    = (const float*)d_in[14];
    float* out = (float*)d_out;

    int n = in_sizes[0] / DIM;   // 50000
    int e = in_sizes[1];         // 800000

    float *qkv, *t;
    cudaGetSymbolAddress((void**)&qkv, g_qkv);
    cudaGetSymbolAddress((void**)&t,   g_t);
    float *Wcat, *bcat;
    cudaGetSymbolAddress((void**)&Wcat, g_Wcat);
    cudaGetSymbolAddress((void**)&bcat, g_bcat);

    // 1) fuse rel_att/rel_msg into projection weights
    prep_weights<<<(128 * 384 + 255) / 256, 256>>>(Wq, bq, Wk, bk, Wv, bv, rel_att, rel_msg);

    // 2) CSR by dst
    zero_deg<<<(n + 255) / 256, 256>>>(n);
    hist_kernel<<<(e + 255) / 256, 256>>>(dst, e);
    alloc_kernel<<<(n + 255) / 256, 256>>>(n);
    scatter_kernel<<<(e + 255) / 256, 256>>>(src, dst, e);

    // 3) fused projection GEMM: [n,128] @ [128,384] -> q | k' | v'
    {
        dim3 grid(384 / BN, (n + BM - 1) / BM);
        gemm_kernel<<<grid, 256>>>(h, Wcat, bcat, qkv, n, 384, DIM, nullptr, nullptr);
    }

    // 4) per-node online-softmax attention + aggregation
    attn_kernel<<<(n * 32 + 255) / 256, 256>>>(rel_pri, n);

    // 5) output GEMM with skip-mix epilogue
    {
        dim3 grid(DIM / BN, (n + BM - 1) / BM);
        gemm_kernel<<<grid, 256>>>(t, Wa, ba, out, n, DIM, DIM, skip, h);
    }
}

// round 15
// speedup vs baseline: 1.4042x; 1.0512x over previous
#include <cuda_runtime.h>
#include <cstdint>
#include <math.h>

#define N_NODES 50000
#define N_EDGES 800000
#define DIM     128
#define HEADS   8
#define DK      16

// ---------------- scratch (no allocations allowed) ----------------
__device__ float g_qkv[(size_t)N_NODES * 384];   // [N][q(128) | k'(128) | v'(128)]
__device__ float g_t[(size_t)N_NODES * DIM];     // aggregated messages
__device__ float g_Wcat[128 * 384];              // fused [Wq | Wk@blkdiag(rel_att) | Wv@blkdiag(rel_msg)]
__device__ float g_bcat[384];
__device__ int   g_deg[N_NODES];
__device__ int   g_offs[N_NODES];
__device__ int   g_cursor[N_NODES];
__device__ int   g_src_sorted[N_EDGES];
__device__ int   g_total;

// ---------------- weight fusion ----------------
__global__ void prep_weights(const float* __restrict__ Wq, const float* __restrict__ bq,
                             const float* __restrict__ Wk, const float* __restrict__ bk,
                             const float* __restrict__ Wv, const float* __restrict__ bv,
                             const float* __restrict__ rel_att, const float* __restrict__ rel_msg)
{
    int idx = blockIdx.x * blockDim.x + threadIdx.x;
    if (idx < 128 * 384) {
        int k = idx / 384, c = idx % 384;
        float val;
        if (c < 128) {
            val = Wq[k * 128 + c];
        } else if (c < 256) {
            int cc = c - 128, hh = cc >> 4, j = cc & 15;
            float s = 0.f;
            #pragma unroll
            for (int l = 0; l < 16; l++)
                s += Wk[k * 128 + hh * 16 + l] * rel_att[hh * 256 + l * 16 + j];
            val = s;
        } else {
            int cc = c - 256, hh = cc >> 4, j = cc & 15;
            float s = 0.f;
            #pragma unroll
            for (int l = 0; l < 16; l++)
                s += Wv[k * 128 + hh * 16 + l] * rel_msg[hh * 256 + l * 16 + j];
            val = s;
        }
        g_Wcat[idx] = val;
    }
    if (idx < 384) {
        int c = idx;
        float val;
        if (c < 128) {
            val = bq[c];
        } else if (c < 256) {
            int cc = c - 128, hh = cc >> 4, j = cc & 15;
            float s = 0.f;
            #pragma unroll
            for (int l = 0; l < 16; l++)
                s += bk[hh * 16 + l] * rel_att[hh * 256 + l * 16 + j];
            val = s;
        } else {
            int cc = c - 256, hh = cc >> 4, j = cc & 15;
            float s = 0.f;
            #pragma unroll
            for (int l = 0; l < 16; l++)
                s += bv[hh * 16 + l] * rel_msg[hh * 256 + l * 16 + j];
            val = s;
        }
        g_bcat[c] = val;
    }
}

// ---------------- CSR build ----------------
__global__ void zero_deg(int n)
{
    int i = blockIdx.x * blockDim.x + threadIdx.x;
    if (i < n) g_deg[i] = 0;
    if (i == 0) g_total = 0;
}

__global__ void hist_kernel(const int* __restrict__ dst, int e)
{
    int i = blockIdx.x * blockDim.x + threadIdx.x;
    if (i < e) atomicAdd(&g_deg[dst[i]], 1);
}

__global__ void alloc_kernel(int n)
{
    int i = blockIdx.x * blockDim.x + threadIdx.x;
    int lane = threadIdx.x & 31;
    int d = (i < n) ? g_deg[i] : 0;
    int incl = d;
    #pragma unroll
    for (int off = 1; off < 32; off <<= 1) {
        int v = __shfl_up_sync(0xffffffffu, incl, off);
        if (lane >= off) incl += v;
    }
    int wtot = __shfl_sync(0xffffffffu, incl, 31);
    int base = 0;
    if (lane == 31 && wtot > 0) base = atomicAdd(&g_total, wtot);
    base = __shfl_sync(0xffffffffu, base, 31);
    if (i < n) {
        int off = base + incl - d;
        g_offs[i] = off;
        g_cursor[i] = off;
    }
}

__global__ void scatter_kernel(const int* __restrict__ src, const int* __restrict__ dst, int e)
{
    int i = blockIdx.x * blockDim.x + threadIdx.x;
    if (i < e) {
        int pos = atomicAdd(&g_cursor[dst[i]], 1);
        g_src_sorted[pos] = src[i];
    }
}

// ---------------- FFMA2 GEMM: BM=128, BN=128, BK=16, double-buffered ----------------
// 256 threads. trow = tid>>5 (0..7) -> rows trow*16..+15 (8 M-adjacent pairs).
// tcol = tid&31 -> cols tcol*4..+3. A-pairs come free from ulonglong2 LDS of
// As[k][m] (M-adjacent floats); only B needs a DUP mov per value.

#define BMg 128
#define BNg 128
#define BKg 16

#define FMA2(d, a, b) asm("fma.rn.f32x2 %0, %1, %2, %0;" : "+l"(d) : "l"(a), "l"(b))
#define DUP2(d, v) asm("mov.b64 %0, {%1, %1};" : "=l"(d) : "f"(v))
#define UNPACK2(lo, hi, s) asm("mov.b64 {%0, %1}, %2;" : "=f"(lo), "=f"(hi) : "l"(s))

__device__ __forceinline__ void cp_async16(void* smem, const void* gmem)
{
    unsigned s = (unsigned)__cvta_generic_to_shared(smem);
    asm volatile("cp.async.cg.shared.global [%0], [%1], 16;" :: "r"(s), "l"(gmem));
}

__global__ void __launch_bounds__(256, 2)
gemm_kernel(const float* __restrict__ A, const float* __restrict__ B,
            const float* __restrict__ bias, float* __restrict__ C,
            int M, int N, int K,
            const float* __restrict__ skip, const float* __restrict__ resid)
{
    __shared__ float As[2][BKg][BMg + 4];
    __shared__ float Bs[2][BKg][BNg];

    int tid = threadIdx.x;
    int block_row = blockIdx.y * BMg;
    int block_col = blockIdx.x * BNg;
    int tcol = tid & 31;
    int trow = tid >> 5;

    unsigned long long acc2[8][4];
    #pragma unroll
    for (int i = 0; i < 8; i++)
        #pragma unroll
        for (int j = 0; j < 4; j++) acc2[i][j] = 0ull;

    // per-thread load map
    // A: 512 float4/stage, 2 per thread: idx=tid+it*256, r=idx>>2 (0..127), kk4=(idx&3)*4
    // B: 512 float4/stage, 2 per thread: idx=tid+it*256, kk=idx>>5? no: kk=idx>>5 gives 0..15 with c=(idx&31)*4
    int ar[2], ak[2], bk_[2], bc[2];
    #pragma unroll
    for (int it = 0; it < 2; it++) {
        int idx = tid + it * 256;
        ar[it] = idx >> 2;
        ak[it] = (idx & 3) * 4;
        bk_[it] = idx >> 5;
        bc[it] = (idx & 31) * 4;
    }

    const int NS = K / BKg;

    // ---- prologue: stage 0 ----
    {
        #pragma unroll
        for (int it = 0; it < 2; it++) {
            int grow = block_row + ar[it];
            float4 v = make_float4(0.f, 0.f, 0.f, 0.f);
            if (grow < M) v = *(const float4*)&A[(size_t)grow * K + ak[it]];
            As[0][ak[it] + 0][ar[it]] = v.x;
            As[0][ak[it] + 1][ar[it]] = v.y;
            As[0][ak[it] + 2][ar[it]] = v.z;
            As[0][ak[it] + 3][ar[it]] = v.w;
            cp_async16(&Bs[0][bk_[it]][bc[it]],
                       &B[(size_t)bk_[it] * N + block_col + bc[it]]);
        }
        asm volatile("cp.async.commit_group;");
        asm volatile("cp.async.wait_group 0;");
        __syncthreads();
    }

    int p = 0;
    #pragma unroll 1
    for (int s = 0; s < NS; s++) {
        float4 aN[2];
        int next = s + 1;
        if (next < NS) {
            #pragma unroll
            for (int it = 0; it < 2; it++) {
                int grow = block_row + ar[it];
                aN[it] = make_float4(0.f, 0.f, 0.f, 0.f);
                if (grow < M) aN[it] = *(const float4*)&A[(size_t)grow * K + next * BKg + ak[it]];
                cp_async16(&Bs[p ^ 1][bk_[it]][bc[it]],
                           &B[(size_t)(next * BKg + bk_[it]) * N + block_col + bc[it]]);
            }
            asm volatile("cp.async.commit_group;");
        }

        #pragma unroll
        for (int kk = 0; kk < BKg; kk++) {
            const ulonglong2* ap = (const ulonglong2*)&As[p][kk][trow * 16];
            ulonglong2 a01 = ap[0];   // pairs {m,m+1} packed for free
            ulonglong2 a23 = ap[1];
            ulonglong2 a45 = ap[2];
            ulonglong2 a67 = ap[3];
            float4 b = *(const float4*)&Bs[p][kk][tcol * 4];
            unsigned long long db0, db1, db2, db3;
            DUP2(db0, b.x); DUP2(db1, b.y); DUP2(db2, b.z); DUP2(db3, b.w);
            FMA2(acc2[0][0], a01.x, db0); FMA2(acc2[0][1], a01.x, db1);
            FMA2(acc2[0][2], a01.x, db2); FMA2(acc2[0][3], a01.x, db3);
            FMA2(acc2[1][0], a01.y, db0); FMA2(acc2[1][1], a01.y, db1);
            FMA2(acc2[1][2], a01.y, db2); FMA2(acc2[1][3], a01.y, db3);
            FMA2(acc2[2][0], a23.x, db0); FMA2(acc2[2][1], a23.x, db1);
            FMA2(acc2[2][2], a23.x, db2); FMA2(acc2[2][3], a23.x, db3);
            FMA2(acc2[3][0], a23.y, db0); FMA2(acc2[3][1], a23.y, db1);
            FMA2(acc2[3][2], a23.y, db2); FMA2(acc2[3][3], a23.y, db3);
            FMA2(acc2[4][0], a45.x, db0); FMA2(acc2[4][1], a45.x, db1);
            FMA2(acc2[4][2], a45.x, db2); FMA2(acc2[4][3], a45.x, db3);
            FMA2(acc2[5][0], a45.y, db0); FMA2(acc2[5][1], a45.y, db1);
            FMA2(acc2[5][2], a45.y, db2); FMA2(acc2[5][3], a45.y, db3);
            FMA2(acc2[6][0], a67.x, db0); FMA2(acc2[6][1], a67.x, db1);
            FMA2(acc2[6][2], a67.x, db2); FMA2(acc2[6][3], a67.x, db3);
            FMA2(acc2[7][0], a67.y, db0); FMA2(acc2[7][1], a67.y, db1);
            FMA2(acc2[7][2], a67.y, db2); FMA2(acc2[7][3], a67.y, db3);
        }

        if (next < NS) {
            #pragma unroll
            for (int it = 0; it < 2; it++) {
                As[p ^ 1][ak[it] + 0][ar[it]] = aN[it].x;
                As[p ^ 1][ak[it] + 1][ar[it]] = aN[it].y;
                As[p ^ 1][ak[it] + 2][ar[it]] = aN[it].z;
                As[p ^ 1][ak[it] + 3][ar[it]] = aN[it].w;
            }
            asm volatile("cp.async.wait_group 0;");
            __syncthreads();
            p ^= 1;
        }
    }

    float alpha = 1.f, beta = 0.f;
    if (skip) {
        float a = 1.f / (1.f + __expf(-skip[0]));
        alpha = a;
        beta = 1.f - a;
    }
    int gcol = block_col + tcol * 4;
    float4 bb = *(const float4*)&bias[gcol];
    #pragma unroll
    for (int pi = 0; pi < 8; pi++) {
        float r0[4], r1[4];
        #pragma unroll
        for (int j = 0; j < 4; j++) UNPACK2(r0[j], r1[j], acc2[pi][j]);
        #pragma unroll
        for (int half = 0; half < 2; half++) {
            int grow = block_row + trow * 16 + 2 * pi + half;
            if (grow < M) {
                float* rr = half ? r1 : r0;
                float4 r;
                r.x = rr[0] + bb.x;
                r.y = rr[1] + bb.y;
                r.z = rr[2] + bb.z;
                r.w = rr[3] + bb.w;
                if (skip) {
                    const float4 h4 = *(const float4*)&resid[(size_t)grow * N + gcol];
                    r.x = r.x * alpha + h4.x * beta;
                    r.y = r.y * alpha + h4.y * beta;
                    r.z = r.z * alpha + h4.z * beta;
                    r.w = r.w * alpha + h4.w * beta;
                }
                *(float4*)&C[(size_t)grow * N + gcol] = r;
            }
        }
    }
}

// ---------------- fused per-node online-softmax aggregation ----------------
__global__ void attn_kernel(const float* __restrict__ rel_pri, int n)
{
    int warp = (blockIdx.x * blockDim.x + threadIdx.x) >> 5;
    if (warp >= n) return;
    int lane = threadIdx.x & 31;
    int head = lane >> 2;

    const float qs = rel_pri[head] * 0.25f;   // rel_pri / sqrt(DK)
    float4 q = *(const float4*)&g_qkv[(size_t)warp * 384 + lane * 4];
    q.x *= qs; q.y *= qs; q.z *= qs; q.w *= qs;

    float m = -INFINITY, ssum = 0.f;
    float4 acc = make_float4(0.f, 0.f, 0.f, 0.f);

    int e0 = g_offs[warp], e1 = e0 + g_deg[warp];
    int s_next = (e0 < e1) ? g_src_sorted[e0] : 0;
    for (int e = e0; e < e1; e++) {
        int s = s_next;
        if (e + 1 < e1) s_next = g_src_sorted[e + 1];
        const float* row = &g_qkv[(size_t)s * 384];
        float4 k4 = *(const float4*)&row[128 + lane * 4];
        float4 v4 = *(const float4*)&row[256 + lane * 4];
        float p = q.x * k4.x + q.y * k4.y + q.z * k4.z + q.w * k4.w;
        p += __shfl_xor_sync(0xffffffffu, p, 1);
        p += __shfl_xor_sync(0xffffffffu, p, 2);
        float nm = fmaxf(m, p);
        float scale = __expf(m - nm);
        float w = __expf(p - nm);
        m = nm;
        ssum = ssum * scale + w;
        acc.x = acc.x * scale + w * v4.x;
        acc.y = acc.y * scale + w * v4.y;
        acc.z = acc.z * scale + w * v4.z;
        acc.w = acc.w * scale + w * v4.w;
    }
    float inv = (ssum > 0.f) ? (1.f / ssum) : 0.f;
    float4 out = make_float4(acc.x * inv, acc.y * inv, acc.z * inv, acc.w * inv);
    *(float4*)&g_t[(size_t)warp * DIM + lane * 4] = out;
}

// ---------------- launcher ----------------
extern "C" void kernel_launch(void* const* d_in, const int* in_sizes, int n_in,
                              void* d_out, int out_size)
{
    const float* h       = (const float*)d_in[0];
    const int*   src     = (const int*)  d_in[1];
    const int*   dst     = (const int*)  d_in[2];
    const float* Wk      = (const float*)d_in[3];
    const float* bk      = (const float*)d_in[4];
    const float* Wq      = (const float*)d_in[5];
    const float* bq      = (const float*)d_in[6];
    const float* Wv      = (const float*)d_in[7];
    const float* bv      = (const float*)d_in[8];
    const float* Wa      = (const float*)d_in[9];
    const float* ba      = (const float*)d_in[10];
    const float* rel_att = (const float*)d_in[11];
    const float* rel_msg = (const float*)d_in[12];
    const float* rel_pri = (const float*)d_in[13];
    const float* skip    = (const float*)d_in[14];
    float* out = (float*)d_out;

    int n = in_sizes[0] / DIM;   // 50000
    int e = in_sizes[1];         // 800000

    float *qkv, *t;
    cudaGetSymbolAddress((void**)&qkv, g_qkv);
    cudaGetSymbolAddress((void**)&t,   g_t);
    float *Wcat, *bcat;
    cudaGetSymbolAddress((void**)&Wcat, g_Wcat);
    cudaGetSymbolAddress((void**)&bcat, g_bcat);

    // 1) fuse rel_att/rel_msg into projection weights
    prep_weights<<<(128 * 384 + 255) / 256, 256>>>(Wq, bq, Wk, bk, Wv, bv, rel_att, rel_msg);

    // 2) CSR by dst
    zero_deg<<<(n + 255) / 256, 256>>>(n);
    hist_kernel<<<(e + 255) / 256, 256>>>(dst, e);
    alloc_kernel<<<(n + 255) / 256, 256>>>(n);
    scatter_kernel<<<(e + 255) / 256, 256>>>(src, dst, e);

    // 3) fused projection GEMM: [n,128] @ [128,384] -> q | k' | v'
    {
        dim3 grid(384 / BNg, (n + BMg - 1) / BMg);
        gemm_kernel<<<grid, 256>>>(h, Wcat, bcat, qkv, n, 384, DIM, nullptr, nullptr);
    }

    // 4) per-node online-softmax attention + aggregation
    attn_kernel<<<(n * 32 + 255) / 256, 256>>>(rel_pri, n);

    // 5) output GEMM with skip-mix epilogue
    {
        dim3 grid(DIM / BNg, (n + BMg - 1) / BMg);
        gemm_kernel<<<grid, 256>>>(t, Wa, ba, out, n, DIM, DIM, skip, h);
    }
}

// round 16
// speedup vs baseline: 1.4796x; 1.0537x over previous
#include <cuda_runtime.h>
#include <cuda_bf16.h>
#include <cstdint>
#include <math.h>

#define N_NODES 50000
#define N_EDGES 800000
#define DIM     128
#define HEADS   8
#define DK      16
#define M_PAD   50048   // 391 * 128

// ---------------- scratch (no allocations allowed) ----------------
__device__ float g_qkv[(size_t)N_NODES * 384];   // [N][q(128) | k'(128) | v'(128)]
__device__ float g_t[(size_t)N_NODES * DIM];     // aggregated messages
__device__ float g_Wcat[128 * 384];              // fused [Wq | Wk@blkdiag(rel_att) | Wv@blkdiag(rel_msg)]
__device__ float g_bcat[384];
__device__ int   g_deg[N_NODES];
__device__ int   g_offs[N_NODES];
__device__ int   g_cursor[N_NODES];
__device__ int   g_src_sorted[N_EDGES];
__device__ int   g_total;
// split-bf16 operand buffers
__device__ __nv_bfloat16 g_Ah[(size_t)M_PAD * 128];
__device__ __nv_bfloat16 g_Al[(size_t)M_PAD * 128];
__device__ __nv_bfloat16 g_Bh[384 * 128];   // B^T [N][K] for proj GEMM
__device__ __nv_bfloat16 g_Bl[384 * 128];
__device__ __nv_bfloat16 g_B2h[128 * 128];  // B^T for output GEMM (Wa)
__device__ __nv_bfloat16 g_B2l[128 * 128];

// ---------------- weight fusion ----------------
__global__ void prep_weights(const float* __restrict__ Wq, const float* __restrict__ bq,
                             const float* __restrict__ Wk, const float* __restrict__ bk,
                             const float* __restrict__ Wv, const float* __restrict__ bv,
                             const float* __restrict__ rel_att, const float* __restrict__ rel_msg)
{
    int idx = blockIdx.x * blockDim.x + threadIdx.x;
    if (idx < 128 * 384) {
        int k = idx / 384, c = idx % 384;
        float val;
        if (c < 128) {
            val = Wq[k * 128 + c];
        } else if (c < 256) {
            int cc = c - 128, hh = cc >> 4, j = cc & 15;
            float s = 0.f;
            #pragma unroll
            for (int l = 0; l < 16; l++)
                s += Wk[k * 128 + hh * 16 + l] * rel_att[hh * 256 + l * 16 + j];
            val = s;
        } else {
            int cc = c - 256, hh = cc >> 4, j = cc & 15;
            float s = 0.f;
            #pragma unroll
            for (int l = 0; l < 16; l++)
                s += Wv[k * 128 + hh * 16 + l] * rel_msg[hh * 256 + l * 16 + j];
            val = s;
        }
        g_Wcat[idx] = val;
    }
    if (idx < 384) {
        int c = idx;
        float val;
        if (c < 128) {
            val = bq[c];
        } else if (c < 256) {
            int cc = c - 128, hh = cc >> 4, j = cc & 15;
            float s = 0.f;
            #pragma unroll
            for (int l = 0; l < 16; l++)
                s += bk[hh * 16 + l] * rel_att[hh * 256 + l * 16 + j];
            val = s;
        } else {
            int cc = c - 256, hh = cc >> 4, j = cc & 15;
            float s = 0.f;
            #pragma unroll
            for (int l = 0; l < 16; l++)
                s += bv[hh * 16 + l] * rel_msg[hh * 256 + l * 16 + j];
            val = s;
        }
        g_bcat[c] = val;
    }
}

// ---------------- split-bf16 conversions ----------------
__device__ __forceinline__ void split_bf(float x, __nv_bfloat16& h, __nv_bfloat16& l)
{
    h = __float2bfloat16(x);
    l = __float2bfloat16(x - __bfloat162float(h));
}

// src fp32 [M x 128] -> g_Ah/g_Al bf16 [M_PAD x 128], zero-padded rows
__global__ void convert_A(const float* __restrict__ src, int M)
{
    int i4 = blockIdx.x * blockDim.x + threadIdx.x;   // one float4 per thread
    if (i4 >= M_PAD * 32) return;
    int row = i4 >> 5;
    float4 v = make_float4(0.f, 0.f, 0.f, 0.f);
    if (row < M) v = ((const float4*)src)[i4];
    __nv_bfloat16 h0, h1, h2, h3, l0, l1, l2, l3;
    split_bf(v.x, h0, l0); split_bf(v.y, h1, l1);
    split_bf(v.z, h2, l2); split_bf(v.w, h3, l3);
    ((__nv_bfloat162*)g_Ah)[i4 * 2 + 0] = __halves2bfloat162(h0, h1);
    ((__nv_bfloat162*)g_Ah)[i4 * 2 + 1] = __halves2bfloat162(h2, h3);
    ((__nv_bfloat162*)g_Al)[i4 * 2 + 0] = __halves2bfloat162(l0, l1);
    ((__nv_bfloat162*)g_Al)[i4 * 2 + 1] = __halves2bfloat162(l2, l3);
}

// W fp32 [K x N] -> Bh/Bl bf16 [N x K] (transposed)
__global__ void convert_B(const float* __restrict__ W,
                          __nv_bfloat16* __restrict__ Bh, __nv_bfloat16* __restrict__ Bl,
                          int K, int N)
{
    int idx = blockIdx.x * blockDim.x + threadIdx.x;
    if (idx >= K * N) return;
    int k = idx / N, n = idx % N;
    __nv_bfloat16 h, l;
    split_bf(W[idx], h, l);
    Bh[(size_t)n * K + k] = h;
    Bl[(size_t)n * K + k] = l;
}

// ---------------- CSR build ----------------
__global__ void zero_deg(int n)
{
    int i = blockIdx.x * blockDim.x + threadIdx.x;
    if (i < n) g_deg[i] = 0;
    if (i == 0) g_total = 0;
}

__global__ void hist_kernel(const int* __restrict__ dst, int e)
{
    int i = blockIdx.x * blockDim.x + threadIdx.x;
    if (i < e) atomicAdd(&g_deg[dst[i]], 1);
}

__global__ void alloc_kernel(int n)
{
    int i = blockIdx.x * blockDim.x + threadIdx.x;
    int lane = threadIdx.x & 31;
    int d = (i < n) ? g_deg[i] : 0;
    int incl = d;
    #pragma unroll
    for (int off = 1; off < 32; off <<= 1) {
        int v = __shfl_up_sync(0xffffffffu, incl, off);
        if (lane >= off) incl += v;
    }
    int wtot = __shfl_sync(0xffffffffu, incl, 31);
    int base = 0;
    if (lane == 31 && wtot > 0) base = atomicAdd(&g_total, wtot);
    base = __shfl_sync(0xffffffffu, base, 31);
    if (i < n) {
        int off = base + incl - d;
        g_offs[i] = off;
        g_cursor[i] = off;
    }
}

__global__ void scatter_kernel(const int* __restrict__ src, const int* __restrict__ dst, int e)
{
    int i = blockIdx.x * blockDim.x + threadIdx.x;
    if (i < e) {
        int pos = atomicAdd(&g_cursor[dst[i]], 1);
        g_src_sorted[pos] = src[i];
    }
}

// ---------------- split-bf16 tensor-core GEMM ----------------
// C = Ah*Bh + Ah*Bl + Al*Bh (+bias, optional skip epilogue).  fp32 accum.
// CTA 128x64, 8 warps (4x2), warp tile 32x32, BK=16, double-buffered cp.async.

#define GBM 128
#define GBN 64
#define GBK 16
#define GST 24   // smem row stride in bf16 (48B: 16B-aligned rows, conflict-free)

__device__ __forceinline__ void cp_async16(void* smem, const void* gmem)
{
    unsigned s = (unsigned)__cvta_generic_to_shared(smem);
    asm volatile("cp.async.cg.shared.global [%0], [%1], 16;" :: "r"(s), "l"(gmem));
}

#define LDSM_X4(r, addr) \
    asm volatile("ldmatrix.sync.aligned.m8n8.x4.shared.b16 {%0,%1,%2,%3}, [%4];" \
        : "=r"((r)[0]), "=r"((r)[1]), "=r"((r)[2]), "=r"((r)[3]) : "r"(addr))

#define MMA16816(d, a, b0, b1) \
    asm volatile("mma.sync.aligned.m16n8k16.row.col.f32.bf16.bf16.f32 " \
        "{%0,%1,%2,%3}, {%4,%5,%6,%7}, {%8,%9}, {%0,%1,%2,%3};" \
        : "+f"((d)[0]), "+f"((d)[1]), "+f"((d)[2]), "+f"((d)[3]) \
        : "r"((a)[0]), "r"((a)[1]), "r"((a)[2]), "r"((a)[3]), "r"(b0), "r"(b1))

__global__ void __launch_bounds__(256, 2)
gemm_bf3(const __nv_bfloat16* __restrict__ Ah, const __nv_bfloat16* __restrict__ Al,
         const __nv_bfloat16* __restrict__ Bh, const __nv_bfloat16* __restrict__ Bl,
         const float* __restrict__ bias, float* __restrict__ C,
         int M, int N, int K,
         const float* __restrict__ skip, const float* __restrict__ resid)
{
    __shared__ __nv_bfloat16 sA[2][2][GBM][GST];   // [stage][h/l][row][k]
    __shared__ __nv_bfloat16 sB[2][2][GBN][GST];   // [stage][h/l][n][k]  (B^T layout)

    int tid = threadIdx.x;
    int warp = tid >> 5, lane = tid & 31;
    int wm = warp >> 1, wn = warp & 1;
    int brow = blockIdx.y * GBM;
    int bcol = blockIdx.x * GBN;

    float acc[2][4][4];
    #pragma unroll
    for (int mi = 0; mi < 2; mi++)
        #pragma unroll
        for (int ni = 0; ni < 4; ni++)
            #pragma unroll
            for (int r = 0; r < 4; r++) acc[mi][ni][r] = 0.f;

    // per-stage copy: 768 x 16B (A: 512, B: 256), 3 per thread
    #define STAGE_COPY(st, k0)                                                        \
    {                                                                                 \
        _Pragma("unroll")                                                             \
        for (int i = 0; i < 3; i++) {                                                 \
            int idx = tid + i * 256;                                                  \
            if (idx < 512) {                                                          \
                int arr = idx >> 8;                                                   \
                int j = idx & 255;                                                    \
                int row = j >> 1;                                                     \
                int seg = (j & 1) * 8;                                                \
                const __nv_bfloat16* s_ = (arr ? Al : Ah) + (size_t)(brow + row) * K + (k0) + seg; \
                cp_async16(&sA[st][arr][row][seg], s_);                               \
            } else {                                                                  \
                int j = idx - 512;                                                    \
                int arr = j >> 7;                                                     \
                int jj = j & 127;                                                     \
                int row = jj >> 1;                                                    \
                int seg = (jj & 1) * 8;                                               \
                const __nv_bfloat16* s_ = (arr ? Bl : Bh) + (size_t)(bcol + row) * K + (k0) + seg; \
                cp_async16(&sB[st][arr][row][seg], s_);                               \
            }                                                                         \
        }                                                                             \
        asm volatile("cp.async.commit_group;");                                       \
    }

    STAGE_COPY(0, 0);
    const int NS = K / GBK;

    #pragma unroll 1
    for (int s = 0; s < NS; s++) {
        asm volatile("cp.async.wait_group 0;");
        __syncthreads();
        if (s + 1 < NS) STAGE_COPY((s + 1) & 1, (s + 1) * GBK);

        int st = s & 1;
        uint32_t afr[2][2][4];   // [m-tile][h/l][reg]
        #pragma unroll
        for (int mi = 0; mi < 2; mi++) {
            int row = wm * 32 + mi * 16 + (lane & 15);
            int col = (lane >> 4) * 8;
            #pragma unroll
            for (int hl = 0; hl < 2; hl++) {
                uint32_t a = (uint32_t)__cvta_generic_to_shared(&sA[st][hl][row][col]);
                LDSM_X4(afr[mi][hl], a);
            }
        }
        uint32_t bfr[2][2][4];   // [n-group(16)][h/l][reg]
        #pragma unroll
        for (int g = 0; g < 2; g++) {
            int row = wn * 32 + g * 16 + (lane & 7) + ((lane >> 4) * 8);
            int col = ((lane >> 3) & 1) * 8;
            #pragma unroll
            for (int hl = 0; hl < 2; hl++) {
                uint32_t a = (uint32_t)__cvta_generic_to_shared(&sB[st][hl][row][col]);
                LDSM_X4(bfr[g][hl], a);
            }
        }
        #pragma unroll
        for (int mi = 0; mi < 2; mi++)
            #pragma unroll
            for (int ni = 0; ni < 4; ni++) {
                int g = ni >> 1, rp = (ni & 1) * 2;
                MMA16816(acc[mi][ni], afr[mi][0], bfr[g][0][rp], bfr[g][0][rp + 1]); // hi*hi
                MMA16816(acc[mi][ni], afr[mi][0], bfr[g][1][rp], bfr[g][1][rp + 1]); // hi*lo
                MMA16816(acc[mi][ni], afr[mi][1], bfr[g][0][rp], bfr[g][0][rp + 1]); // lo*hi
            }
        __syncthreads();
    }

    float alpha = 1.f, beta = 0.f;
    if (skip) {
        float a = 1.f / (1.f + __expf(-skip[0]));
        alpha = a;
        beta = 1.f - a;
    }
    #pragma unroll
    for (int mi = 0; mi < 2; mi++)
        #pragma unroll
        for (int ni = 0; ni < 4; ni++) {
            int col = bcol + wn * 32 + ni * 8 + (lane & 3) * 2;
            float b0 = bias[col], b1 = bias[col + 1];
            #pragma unroll
            for (int rp = 0; rp < 2; rp++) {
                int row = brow + wm * 32 + mi * 16 + (lane >> 2) + rp * 8;
                if (row < M) {
                    float x0 = acc[mi][ni][rp * 2 + 0] + b0;
                    float x1 = acc[mi][ni][rp * 2 + 1] + b1;
                    if (skip) {
                        const float2 h2 = *(const float2*)&resid[(size_t)row * N + col];
                        x0 = x0 * alpha + h2.x * beta;
                        x1 = x1 * alpha + h2.y * beta;
                    }
                    float2 o; o.x = x0; o.y = x1;
                    *(float2*)&C[(size_t)row * N + col] = o;
                }
            }
        }
}

// ---------------- fused per-node online-softmax aggregation ----------------
__global__ void attn_kernel(const float* __restrict__ rel_pri, int n)
{
    int warp = (blockIdx.x * blockDim.x + threadIdx.x) >> 5;
    if (warp >= n) return;
    int lane = threadIdx.x & 31;
    int head = lane >> 2;

    const float qs = rel_pri[head] * 0.25f;   // rel_pri / sqrt(DK)
    float4 q = *(const float4*)&g_qkv[(size_t)warp * 384 + lane * 4];
    q.x *= qs; q.y *= qs; q.z *= qs; q.w *= qs;

    float m = -INFINITY, ssum = 0.f;
    float4 acc = make_float4(0.f, 0.f, 0.f, 0.f);

    int e0 = g_offs[warp], e1 = e0 + g_deg[warp];
    int s_next = (e0 < e1) ? g_src_sorted[e0] : 0;
    for (int e = e0; e < e1; e++) {
        int s = s_next;
        if (e + 1 < e1) s_next = g_src_sorted[e + 1];
        const float* row = &g_qkv[(size_t)s * 384];
        float4 k4 = *(const float4*)&row[128 + lane * 4];
        float4 v4 = *(const float4*)&row[256 + lane * 4];
        float p = q.x * k4.x + q.y * k4.y + q.z * k4.z + q.w * k4.w;
        p += __shfl_xor_sync(0xffffffffu, p, 1);
        p += __shfl_xor_sync(0xffffffffu, p, 2);
        float nm = fmaxf(m, p);
        float scale = __expf(m - nm);
        float w = __expf(p - nm);
        m = nm;
        ssum = ssum * scale + w;
        acc.x = acc.x * scale + w * v4.x;
        acc.y = acc.y * scale + w * v4.y;
        acc.z = acc.z * scale + w * v4.z;
        acc.w = acc.w * scale + w * v4.w;
    }
    float inv = (ssum > 0.f) ? (1.f / ssum) : 0.f;
    float4 out = make_float4(acc.x * inv, acc.y * inv, acc.z * inv, acc.w * inv);
    *(float4*)&g_t[(size_t)warp * DIM + lane * 4] = out;
}

// ---------------- launcher ----------------
extern "C" void kernel_launch(void* const* d_in, const int* in_sizes, int n_in,
                              void* d_out, int out_size)
{
    const float* h       = (const float*)d_in[0];
    const int*   src     = (const int*)  d_in[1];
    const int*   dst     = (const int*)  d_in[2];
    const float* Wk      = (const float*)d_in[3];
    const float* bk      = (const float*)d_in[4];
    const float* Wq      = (const float*)d_in[5];
    const float* bq      = (const float*)d_in[6];
    const float* Wv      = (const float*)d_in[7];
    const float* bv      = (const float*)d_in[8];
    const float* Wa      = (const float*)d_in[9];
    const float* ba      = (const float*)d_in[10];
    const float* rel_att = (const float*)d_in[11];
    const float* rel_msg = (const float*)d_in[12];
    const float* rel_pri = (const float*)d_in[13];
    const float* skip    = (const float*)d_in[14];
    float* out = (float*)d_out;

    int n = in_sizes[0] / DIM;   // 50000
    int e = in_sizes[1];         // 800000

    float *qkv, *t, *Wcat, *bcat;
    cudaGetSymbolAddress((void**)&qkv,  g_qkv);
    cudaGetSymbolAddress((void**)&t,    g_t);
    cudaGetSymbolAddress((void**)&Wcat, g_Wcat);
    cudaGetSymbolAddress((void**)&bcat, g_bcat);
    __nv_bfloat16 *Ah, *Al, *Bh, *Bl, *B2h, *B2l;
    cudaGetSymbolAddress((void**)&Ah,  g_Ah);
    cudaGetSymbolAddress((void**)&Al,  g_Al);
    cudaGetSymbolAddress((void**)&Bh,  g_Bh);
    cudaGetSymbolAddress((void**)&Bl,  g_Bl);
    cudaGetSymbolAddress((void**)&B2h, g_B2h);
    cudaGetSymbolAddress((void**)&B2l, g_B2l);

    // 1) fuse rel_att/rel_msg into projection weights; split weights to bf16 hi/lo
    prep_weights<<<(128 * 384 + 255) / 256, 256>>>(Wq, bq, Wk, bk, Wv, bv, rel_att, rel_msg);
    convert_B<<<(128 * 384 + 255) / 256, 256>>>(Wcat, Bh, Bl, 128, 384);
    convert_B<<<(128 * 128 + 255) / 256, 256>>>(Wa, B2h, B2l, 128, 128);
    convert_A<<<(M_PAD * 32 + 255) / 256, 256>>>(h, n);

    // 2) CSR by dst
    zero_deg<<<(n + 255) / 256, 256>>>(n);
    hist_kernel<<<(e + 255) / 256, 256>>>(dst, e);
    alloc_kernel<<<(n + 255) / 256, 256>>>(n);
    scatter_kernel<<<(e + 255) / 256, 256>>>(src, dst, e);

    // 3) fused projection GEMM (split-bf16 tensor cores): [n,128]@[128,384] -> q|k'|v'
    {
        dim3 grid(384 / GBN, (n + GBM - 1) / GBM);
        gemm_bf3<<<grid, 256>>>(Ah, Al, Bh, Bl, bcat, qkv, n, 384, DIM, nullptr, nullptr);
    }

    // 4) per-node online-softmax attention + aggregation
    attn_kernel<<<(n * 32 + 255) / 256, 256>>>(rel_pri, n);

    // 5) output GEMM with skip-mix epilogue
    convert_A<<<(M_PAD * 32 + 255) / 256, 256>>>(t, n);
    {
        dim3 grid(DIM / GBN, (n + GBM - 1) / GBM);
        gemm_bf3<<<grid, 256>>>(Ah, Al, B2h, B2l, ba, out, n, DIM, DIM, skip, h);
    }
}

// round 17
// speedup vs baseline: 1.4809x; 1.0009x over previous
#include <cuda_runtime.h>
#include <cuda_bf16.h>
#include <cstdint>
#include <math.h>

#define N_NODES 50000
#define N_EDGES 800000
#define DIM     128
#define HEADS   8
#define DK      16
#define M_PAD   50048   // 391 * 128

// ---------------- scratch (no allocations allowed) ----------------
__device__ float g_qkv[(size_t)N_NODES * 384];   // [N][q(128) | k'(128) | v'(128)]
__device__ float g_t[(size_t)N_NODES * DIM];     // aggregated messages
__device__ float g_Wcat[128 * 384];              // fused [Wq | Wk@blkdiag(rel_att) | Wv@blkdiag(rel_msg)]
__device__ float g_bcat[384];
__device__ int   g_deg[N_NODES];
__device__ int   g_offs[N_NODES];
__device__ int   g_cursor[N_NODES];
__device__ int   g_src_sorted[N_EDGES];
__device__ int   g_total;
// split-bf16 operand buffers
__device__ __nv_bfloat16 g_Ah[(size_t)M_PAD * 128];
__device__ __nv_bfloat16 g_Al[(size_t)M_PAD * 128];
__device__ __nv_bfloat16 g_Bh[384 * 128];   // B^T [N][K] for proj GEMM
__device__ __nv_bfloat16 g_Bl[384 * 128];
__device__ __nv_bfloat16 g_B2h[128 * 128];  // B^T for output GEMM (Wa)
__device__ __nv_bfloat16 g_B2l[128 * 128];

// ---------------- weight fusion ----------------
__global__ void prep_weights(const float* __restrict__ Wq, const float* __restrict__ bq,
                             const float* __restrict__ Wk, const float* __restrict__ bk,
                             const float* __restrict__ Wv, const float* __restrict__ bv,
                             const float* __restrict__ rel_att, const float* __restrict__ rel_msg)
{
    int idx = blockIdx.x * blockDim.x + threadIdx.x;
    if (idx < 128 * 384) {
        int k = idx / 384, c = idx % 384;
        float val;
        if (c < 128) {
            val = Wq[k * 128 + c];
        } else if (c < 256) {
            int cc = c - 128, hh = cc >> 4, j = cc & 15;
            float s = 0.f;
            #pragma unroll
            for (int l = 0; l < 16; l++)
                s += Wk[k * 128 + hh * 16 + l] * rel_att[hh * 256 + l * 16 + j];
            val = s;
        } else {
            int cc = c - 256, hh = cc >> 4, j = cc & 15;
            float s = 0.f;
            #pragma unroll
            for (int l = 0; l < 16; l++)
                s += Wv[k * 128 + hh * 16 + l] * rel_msg[hh * 256 + l * 16 + j];
            val = s;
        }
        g_Wcat[idx] = val;
    }
    if (idx < 384) {
        int c = idx;
        float val;
        if (c < 128) {
            val = bq[c];
        } else if (c < 256) {
            int cc = c - 128, hh = cc >> 4, j = cc & 15;
            float s = 0.f;
            #pragma unroll
            for (int l = 0; l < 16; l++)
                s += bk[hh * 16 + l] * rel_att[hh * 256 + l * 16 + j];
            val = s;
        } else {
            int cc = c - 256, hh = cc >> 4, j = cc & 15;
            float s = 0.f;
            #pragma unroll
            for (int l = 0; l < 16; l++)
                s += bv[hh * 16 + l] * rel_msg[hh * 256 + l * 16 + j];
            val = s;
        }
        g_bcat[c] = val;
    }
}

// ---------------- split-bf16 conversions ----------------
__device__ __forceinline__ void split_bf(float x, __nv_bfloat16& h, __nv_bfloat16& l)
{
    h = __float2bfloat16(x);
    l = __float2bfloat16(x - __bfloat162float(h));
}

// src fp32 [M x 128] -> g_Ah/g_Al bf16 [M_PAD x 128], zero-padded rows
__global__ void convert_A(const float* __restrict__ src, int M)
{
    int i4 = blockIdx.x * blockDim.x + threadIdx.x;   // one float4 per thread
    if (i4 >= M_PAD * 32) return;
    int row = i4 >> 5;
    float4 v = make_float4(0.f, 0.f, 0.f, 0.f);
    if (row < M) v = ((const float4*)src)[i4];
    __nv_bfloat16 h0, h1, h2, h3, l0, l1, l2, l3;
    split_bf(v.x, h0, l0); split_bf(v.y, h1, l1);
    split_bf(v.z, h2, l2); split_bf(v.w, h3, l3);
    ((__nv_bfloat162*)g_Ah)[i4 * 2 + 0] = __halves2bfloat162(h0, h1);
    ((__nv_bfloat162*)g_Ah)[i4 * 2 + 1] = __halves2bfloat162(h2, h3);
    ((__nv_bfloat162*)g_Al)[i4 * 2 + 0] = __halves2bfloat162(l0, l1);
    ((__nv_bfloat162*)g_Al)[i4 * 2 + 1] = __halves2bfloat162(l2, l3);
}

// W fp32 [K x N] -> Bh/Bl bf16 [N x K] (transposed)
__global__ void convert_B(const float* __restrict__ W,
                          __nv_bfloat16* __restrict__ Bh, __nv_bfloat16* __restrict__ Bl,
                          int K, int N)
{
    int idx = blockIdx.x * blockDim.x + threadIdx.x;
    if (idx >= K * N) return;
    int k = idx / N, n = idx % N;
    __nv_bfloat16 h, l;
    split_bf(W[idx], h, l);
    Bh[(size_t)n * K + k] = h;
    Bl[(size_t)n * K + k] = l;
}

// ---------------- CSR build ----------------
__global__ void zero_deg(int n)
{
    int i = blockIdx.x * blockDim.x + threadIdx.x;
    if (i < n) g_deg[i] = 0;
    if (i == 0) g_total = 0;
}

__global__ void hist_kernel(const int* __restrict__ dst, int e)
{
    int i = blockIdx.x * blockDim.x + threadIdx.x;
    if (i < e) atomicAdd(&g_deg[dst[i]], 1);
}

__global__ void alloc_kernel(int n)
{
    int i = blockIdx.x * blockDim.x + threadIdx.x;
    int lane = threadIdx.x & 31;
    int d = (i < n) ? g_deg[i] : 0;
    int incl = d;
    #pragma unroll
    for (int off = 1; off < 32; off <<= 1) {
        int v = __shfl_up_sync(0xffffffffu, incl, off);
        if (lane >= off) incl += v;
    }
    int wtot = __shfl_sync(0xffffffffu, incl, 31);
    int base = 0;
    if (lane == 31 && wtot > 0) base = atomicAdd(&g_total, wtot);
    base = __shfl_sync(0xffffffffu, base, 31);
    if (i < n) {
        int off = base + incl - d;
        g_offs[i] = off;
        g_cursor[i] = off;
    }
}

__global__ void scatter_kernel(const int* __restrict__ src, const int* __restrict__ dst, int e)
{
    int i = blockIdx.x * blockDim.x + threadIdx.x;
    if (i < e) {
        int pos = atomicAdd(&g_cursor[dst[i]], 1);
        g_src_sorted[pos] = src[i];
    }
}

// ---------------- split-bf16 tensor-core GEMM ----------------
// C = Ah*Bh + Ah*Bl + Al*Bh (+bias, optional skip epilogue).  fp32 accum.
// CTA 128x64, 8 warps (4x2), warp tile 32x32, BK=16, double-buffered cp.async.

#define GBM 128
#define GBN 64
#define GBK 16
#define GST 24   // smem row stride in bf16 (48B: 16B-aligned rows, conflict-free)

__device__ __forceinline__ void cp_async16(void* smem, const void* gmem)
{
    unsigned s = (unsigned)__cvta_generic_to_shared(smem);
    asm volatile("cp.async.cg.shared.global [%0], [%1], 16;" :: "r"(s), "l"(gmem));
}

#define LDSM_X4(r, addr) \
    asm volatile("ldmatrix.sync.aligned.m8n8.x4.shared.b16 {%0,%1,%2,%3}, [%4];" \
        : "=r"((r)[0]), "=r"((r)[1]), "=r"((r)[2]), "=r"((r)[3]) : "r"(addr))

#define MMA16816(d, a, b0, b1) \
    asm volatile("mma.sync.aligned.m16n8k16.row.col.f32.bf16.bf16.f32 " \
        "{%0,%1,%2,%3}, {%4,%5,%6,%7}, {%8,%9}, {%0,%1,%2,%3};" \
        : "+f"((d)[0]), "+f"((d)[1]), "+f"((d)[2]), "+f"((d)[3]) \
        : "r"((a)[0]), "r"((a)[1]), "r"((a)[2]), "r"((a)[3]), "r"(b0), "r"(b1))

__global__ void __launch_bounds__(256, 2)
gemm_bf3(const __nv_bfloat16* __restrict__ Ah, const __nv_bfloat16* __restrict__ Al,
         const __nv_bfloat16* __restrict__ Bh, const __nv_bfloat16* __restrict__ Bl,
         const float* __restrict__ bias, float* __restrict__ C,
         int M, int N, int K,
         const float* __restrict__ skip, const float* __restrict__ resid)
{
    __shared__ __nv_bfloat16 sA[2][2][GBM][GST];   // [stage][h/l][row][k]
    __shared__ __nv_bfloat16 sB[2][2][GBN][GST];   // [stage][h/l][n][k]  (B^T layout)

    int tid = threadIdx.x;
    int warp = tid >> 5, lane = tid & 31;
    int wm = warp >> 1, wn = warp & 1;
    int brow = blockIdx.y * GBM;
    int bcol = blockIdx.x * GBN;

    float acc[2][4][4];
    #pragma unroll
    for (int mi = 0; mi < 2; mi++)
        #pragma unroll
        for (int ni = 0; ni < 4; ni++)
            #pragma unroll
            for (int r = 0; r < 4; r++) acc[mi][ni][r] = 0.f;

    // per-stage copy: 768 x 16B (A: 512, B: 256), 3 per thread
    #define STAGE_COPY(st, k0)                                                        \
    {                                                                                 \
        _Pragma("unroll")                                                             \
        for (int i = 0; i < 3; i++) {                                                 \
            int idx = tid + i * 256;                                                  \
            if (idx < 512) {                                                          \
                int arr = idx >> 8;                                                   \
                int j = idx & 255;                                                    \
                int row = j >> 1;                                                     \
                int seg = (j & 1) * 8;                                                \
                const __nv_bfloat16* s_ = (arr ? Al : Ah) + (size_t)(brow + row) * K + (k0) + seg; \
                cp_async16(&sA[st][arr][row][seg], s_);                               \
            } else {                                                                  \
                int j = idx - 512;                                                    \
                int arr = j >> 7;                                                     \
                int jj = j & 127;                                                     \
                int row = jj >> 1;                                                    \
                int seg = (jj & 1) * 8;                                               \
                const __nv_bfloat16* s_ = (arr ? Bl : Bh) + (size_t)(bcol + row) * K + (k0) + seg; \
                cp_async16(&sB[st][arr][row][seg], s_);                               \
            }                                                                         \
        }                                                                             \
        asm volatile("cp.async.commit_group;");                                       \
    }

    STAGE_COPY(0, 0);
    const int NS = K / GBK;

    #pragma unroll 1
    for (int s = 0; s < NS; s++) {
        asm volatile("cp.async.wait_group 0;");
        __syncthreads();
        if (s + 1 < NS) STAGE_COPY((s + 1) & 1, (s + 1) * GBK);

        int st = s & 1;
        uint32_t afr[2][2][4];   // [m-tile][h/l][reg]
        #pragma unroll
        for (int mi = 0; mi < 2; mi++) {
            int row = wm * 32 + mi * 16 + (lane & 15);
            int col = (lane >> 4) * 8;
            #pragma unroll
            for (int hl = 0; hl < 2; hl++) {
                uint32_t a = (uint32_t)__cvta_generic_to_shared(&sA[st][hl][row][col]);
                LDSM_X4(afr[mi][hl], a);
            }
        }
        uint32_t bfr[2][2][4];   // [n-group(16)][h/l][reg]
        #pragma unroll
        for (int g = 0; g < 2; g++) {
            int row = wn * 32 + g * 16 + (lane & 7) + ((lane >> 4) * 8);
            int col = ((lane >> 3) & 1) * 8;
            #pragma unroll
            for (int hl = 0; hl < 2; hl++) {
                uint32_t a = (uint32_t)__cvta_generic_to_shared(&sB[st][hl][row][col]);
                LDSM_X4(bfr[g][hl], a);
            }
        }
        #pragma unroll
        for (int mi = 0; mi < 2; mi++)
            #pragma unroll
            for (int ni = 0; ni < 4; ni++) {
                int g = ni >> 1, rp = (ni & 1) * 2;
                MMA16816(acc[mi][ni], afr[mi][0], bfr[g][0][rp], bfr[g][0][rp + 1]); // hi*hi
                MMA16816(acc[mi][ni], afr[mi][0], bfr[g][1][rp], bfr[g][1][rp + 1]); // hi*lo
                MMA16816(acc[mi][ni], afr[mi][1], bfr[g][0][rp], bfr[g][0][rp + 1]); // lo*hi
            }
        __syncthreads();
    }

    float alpha = 1.f, beta = 0.f;
    if (skip) {
        float a = 1.f / (1.f + __expf(-skip[0]));
        alpha = a;
        beta = 1.f - a;
    }
    #pragma unroll
    for (int mi = 0; mi < 2; mi++)
        #pragma unroll
        for (int ni = 0; ni < 4; ni++) {
            int col = bcol + wn * 32 + ni * 8 + (lane & 3) * 2;
            float b0 = bias[col], b1 = bias[col + 1];
            #pragma unroll
            for (int rp = 0; rp < 2; rp++) {
                int row = brow + wm * 32 + mi * 16 + (lane >> 2) + rp * 8;
                if (row < M) {
                    float x0 = acc[mi][ni][rp * 2 + 0] + b0;
                    float x1 = acc[mi][ni][rp * 2 + 1] + b1;
                    if (skip) {
                        const float2 h2 = *(const float2*)&resid[(size_t)row * N + col];
                        x0 = x0 * alpha + h2.x * beta;
                        x1 = x1 * alpha + h2.y * beta;
                    }
                    float2 o; o.x = x0; o.y = x1;
                    *(float2*)&C[(size_t)row * N + col] = o;
                }
            }
        }
}

// ---------------- fused per-node online-softmax aggregation ----------------
__global__ void attn_kernel(const float* __restrict__ rel_pri, int n)
{
    int warp = (blockIdx.x * blockDim.x + threadIdx.x) >> 5;
    if (warp >= n) return;
    int lane = threadIdx.x & 31;
    int head = lane >> 2;

    const float qs = rel_pri[head] * 0.25f;   // rel_pri / sqrt(DK)
    float4 q = *(const float4*)&g_qkv[(size_t)warp * 384 + lane * 4];
    q.x *= qs; q.y *= qs; q.z *= qs; q.w *= qs;

    float m = -INFINITY, ssum = 0.f;
    float4 acc = make_float4(0.f, 0.f, 0.f, 0.f);

    int e0 = g_offs[warp], e1 = e0 + g_deg[warp];
    int s_next = (e0 < e1) ? g_src_sorted[e0] : 0;
    for (int e = e0; e < e1; e++) {
        int s = s_next;
        if (e + 1 < e1) s_next = g_src_sorted[e + 1];
        const float* row = &g_qkv[(size_t)s * 384];
        float4 k4 = *(const float4*)&row[128 + lane * 4];
        float4 v4 = *(const float4*)&row[256 + lane * 4];
        float p = q.x * k4.x + q.y * k4.y + q.z * k4.z + q.w * k4.w;
        p += __shfl_xor_sync(0xffffffffu, p, 1);
        p += __shfl_xor_sync(0xffffffffu, p, 2);
        float nm = fmaxf(m, p);
        float scale = __expf(m - nm);
        float w = __expf(p - nm);
        m = nm;
        ssum = ssum * scale + w;
        acc.x = acc.x * scale + w * v4.x;
        acc.y = acc.y * scale + w * v4.y;
        acc.z = acc.z * scale + w * v4.z;
        acc.w = acc.w * scale + w * v4.w;
    }
    float inv = (ssum > 0.f) ? (1.f / ssum) : 0.f;
    float4 out = make_float4(acc.x * inv, acc.y * inv, acc.z * inv, acc.w * inv);
    *(float4*)&g_t[(size_t)warp * DIM + lane * 4] = out;
}

// ---------------- launcher ----------------
extern "C" void kernel_launch(void* const* d_in, const int* in_sizes, int n_in,
                              void* d_out, int out_size)
{
    const float* h       = (const float*)d_in[0];
    const int*   src     = (const int*)  d_in[1];
    const int*   dst     = (const int*)  d_in[2];
    const float* Wk      = (const float*)d_in[3];
    const float* bk      = (const float*)d_in[4];
    const float* Wq      = (const float*)d_in[5];
    const float* bq      = (const float*)d_in[6];
    const float* Wv      = (const float*)d_in[7];
    const float* bv      = (const float*)d_in[8];
    const float* Wa      = (const float*)d_in[9];
    const float* ba      = (const float*)d_in[10];
    const float* rel_att = (const float*)d_in[11];
    const float* rel_msg = (const float*)d_in[12];
    const float* rel_pri = (const float*)d_in[13];
    const float* skip    = (const float*)d_in[14];
    float* out = (float*)d_out;

    int n = in_sizes[0] / DIM;   // 50000
    int e = in_sizes[1];         // 800000

    float *qkv, *t, *Wcat, *bcat;
    cudaGetSymbolAddress((void**)&qkv,  g_qkv);
    cudaGetSymbolAddress((void**)&t,    g_t);
    cudaGetSymbolAddress((void**)&Wcat, g_Wcat);
    cudaGetSymbolAddress((void**)&bcat, g_bcat);
    __nv_bfloat16 *Ah, *Al, *Bh, *Bl, *B2h, *B2l;
    cudaGetSymbolAddress((void**)&Ah,  g_Ah);
    cudaGetSymbolAddress((void**)&Al,  g_Al);
    cudaGetSymbolAddress((void**)&Bh,  g_Bh);
    cudaGetSymbolAddress((void**)&Bl,  g_Bl);
    cudaGetSymbolAddress((void**)&B2h, g_B2h);
    cudaGetSymbolAddress((void**)&B2l, g_B2l);

    // 1) fuse rel_att/rel_msg into projection weights; split weights to bf16 hi/lo
    prep_weights<<<(128 * 384 + 255) / 256, 256>>>(Wq, bq, Wk, bk, Wv, bv, rel_att, rel_msg);
    convert_B<<<(128 * 384 + 255) / 256, 256>>>(Wcat, Bh, Bl, 128, 384);
    convert_B<<<(128 * 128 + 255) / 256, 256>>>(Wa, B2h, B2l, 128, 128);
    convert_A<<<(M_PAD * 32 + 255) / 256, 256>>>(h, n);

    // 2) CSR by dst
    zero_deg<<<(n + 255) / 256, 256>>>(n);
    hist_kernel<<<(e + 255) / 256, 256>>>(dst, e);
    alloc_kernel<<<(n + 255) / 256, 256>>>(n);
    scatter_kernel<<<(e + 255) / 256, 256>>>(src, dst, e);

    // 3) fused projection GEMM (split-bf16 tensor cores): [n,128]@[128,384] -> q|k'|v'
    {
        dim3 grid(384 / GBN, (n + GBM - 1) / GBM);
        gemm_bf3<<<grid, 256>>>(Ah, Al, Bh, Bl, bcat, qkv, n, 384, DIM, nullptr, nullptr);
    }

    // 4) per-node online-softmax attention + aggregation
    attn_kernel<<<(n * 32 + 255) / 256, 256>>>(rel_pri, n);

    // 5) output GEMM with skip-mix epilogue
    convert_A<<<(M_PAD * 32 + 255) / 256, 256>>>(t, n);
    {
        dim3 grid(DIM / GBN, (n + GBM - 1) / GBM);
        gemm_bf3<<<grid, 256>>>(Ah, Al, B2h, B2l, ba, out, n, DIM, DIM, skip, h);
    }
}